// round 3
// baseline (speedup 1.0000x reference)
#include <cuda_runtime.h>
#include <math.h>

#define Bq 4096
#define Sq 512
#define NT 512
#define NB 128
#define RPB 32
#define HSTR 68              // padded h row stride (floats) -> bank-conflict-free rl access
#define HBUF (RPB*HSTR)      // 2176 floats per h buffer

typedef unsigned long long ull;

// shared layout (float offsets)
#define O_WPH  0                      // packed whh  [32 kk][256 g] x2  = 16384
#define O_WPI  (O_WPH + 16384)        // packed w_ih [6 kk][256 g] x2   = 3072
#define O_PRE  (O_WPI + 3072)         // pre [32][256]                  = 8192
#define O_GATE (O_PRE + 8192)         // gates [32][256]                = 8192
#define O_H2   (O_GATE + 8192)        // h double buffer 2*[32][HSTR]   = 4352
#define O_C    (O_H2 + 2*HBUF)        // c [32][64]                     = 2048
#define O_X    (O_C + 2048)           // x [32][12]                     = 384
#define O_WOUT (O_X + 384)            // w_out [64][2]                  = 128
#define O_SC   (O_WOUT + 128)
#define O_ISC  (O_SC + 32)
#define SM_TOTAL (O_ISC + 32)
#define SMEM_BYTES (SM_TOTAL*4)

__device__ __forceinline__ float sigf(float x){ return 1.0f/(1.0f+__expf(-x)); }
__device__ __forceinline__ float tanh_f(float x){ return 2.0f/(1.0f+__expf(-2.0f*x)) - 1.0f; }

__device__ __forceinline__ void ffma2(ull &d, ull a, ull b){
    asm("fma.rn.f32x2 %0, %1, %2, %0;" : "+l"(d) : "l"(a), "l"(b));
}
__device__ __forceinline__ float2 unpack2(ull v){
    float2 f; asm("mov.b64 {%0,%1}, %2;" : "=f"(f.x), "=f"(f.y) : "l"(v)); return f;
}

__global__ void __launch_bounds__(NT,1)
deepar_kernel(const float* __restrict__ target,
              const float* __restrict__ covar,
              const int*   __restrict__ cats,
              const float* __restrict__ scale,
              const float* __restrict__ e0,
              const float* __restrict__ e1,
              const float* __restrict__ e2,
              const float* __restrict__ e3,
              const float* __restrict__ w_ih,
              const float* __restrict__ w_hh,
              const float* __restrict__ bias,
              const float* __restrict__ w_out,
              const float* __restrict__ b_out,
              float* __restrict__ out)
{
    extern __shared__ float sm[];
    float* wph_s   = sm + O_WPH;
    float* wpi_s   = sm + O_WPI;
    float* pre_s   = sm + O_PRE;
    float* gates_s = sm + O_GATE;
    float* h2_s    = sm + O_H2;
    float* c_s     = sm + O_C;
    float* x_s     = sm + O_X;
    float* wout_s  = sm + O_WOUT;
    float* sc_s    = sm + O_SC;
    float* isc_s   = sm + O_ISC;
    float* sx_s    = gates_s;          // alias: static_x [32][66], pre-loop only

    const int tid  = threadIdx.x;
    const int row0 = blockIdx.x * RPB;

    // ---- repack weights into shared (k-pair packing for f32x2) ----
    for (int i = tid; i < 32*256; i += NT){
        int kk = i >> 8, g = i & 255;
        wph_s[2*i]   = w_hh[(2*kk)*256 + g];
        wph_s[2*i+1] = w_hh[(2*kk+1)*256 + g];
    }
    for (int i = tid; i < 6*256; i += NT){
        int kk = i >> 8, g = i & 255;
        wpi_s[2*i]   = w_ih[(2*kk)*256 + g];
        wpi_s[2*i+1] = (2*kk+1 < 11) ? w_ih[(2*kk+1)*256 + g] : 0.0f;
    }
    if (tid < 128) wout_s[tid] = w_out[tid];
    if (tid < RPB){
        float s = scale[row0 + tid];
        sc_s[tid]  = s;
        isc_s[tid] = 1.0f / fmaxf(s, 1e-4f);
    }
    // zero h buffers + c
    for (int i = tid; i < 2*HBUF; i += NT) h2_s[i] = 0.0f;
    for (int i = tid; i < RPB*64; i += NT) c_s[i] = 0.0f;

    // ---- static_x staging into sx_s[32][66] ----
    for (int e = tid; e < RPB*65; e += NT){
        int r = e / 65, j = e - r*65;
        int b = row0 + r;
        float v;
        if (j < 64){
            int tsel = j >> 4, jj = j & 15;
            int c = cats[b*4 + tsel];
            const float* et = (tsel==0)?e0:(tsel==1)?e1:(tsel==2)?e2:e3;
            v = et[c*16 + jj];
        } else {
            v = log1pf(scale[b]);
        }
        sx_s[r*66 + j] = v;
    }
    __syncthreads();

    // ---- 2D lane tiling ----
    const int lane   = tid & 31;
    const int wrp    = tid >> 5;        // 16 warps
    const int warp_g = wrp & 7;         // gate tile (8 x 32 gates)
    const int warp_r = wrp >> 3;        // row tile  (2 x 16 rows)
    const int gl     = lane & 7;        // 8 gate groups / warp
    const int rl     = lane >> 3;       // 4 row groups / warp
    const int gbase  = warp_g*32 + gl*4;          // 4 gates per thread
    const int rA     = warp_r*16 + rl;            // rows: rA + 4*j, j=0..3

    // ---- precompute pre = bias + static_x @ w_ih[11:76] into pre_s ----
    {
        float accp[4][4];
        float4 bv = *(const float4*)(bias + gbase);
        #pragma unroll
        for (int j = 0; j < 4; j++){
            accp[j][0]=bv.x; accp[j][1]=bv.y; accp[j][2]=bv.z; accp[j][3]=bv.w;
        }
        for (int k = 0; k < 65; k++){
            float4 w = *(const float4*)(w_ih + (11+k)*256 + gbase);
            #pragma unroll
            for (int j = 0; j < 4; j++){
                float xv = sx_s[(rA + 4*j)*66 + k];
                accp[j][0] = fmaf(xv, w.x, accp[j][0]);
                accp[j][1] = fmaf(xv, w.y, accp[j][1]);
                accp[j][2] = fmaf(xv, w.z, accp[j][2]);
                accp[j][3] = fmaf(xv, w.w, accp[j][3]);
            }
        }
        __syncthreads();   // sx_s (gates_s alias) readers done before pre/gates writes
        #pragma unroll
        for (int j = 0; j < 4; j++){
            float4 p; p.x=accp[j][0]; p.y=accp[j][1]; p.z=accp[j][2]; p.w=accp[j][3];
            *(float4*)(pre_s + (rA + 4*j)*256 + gbase) = p;
        }
    }

    // ---- per-thread x prefetch slot (tid < 384): r = tid/12, j = tid%12 ----
    int xr = 0, xj = 0, xb = 0;
    float xreg = 0.0f;
    if (tid < RPB*12){
        xr = tid / 12; xj = tid - xr*12; xb = row0 + xr;
        if (xj >= 1 && xj <= 10) xreg = covar[(xb*Sq + 0)*10 + (xj-1)];
        x_s[tid] = xreg;   // x(t=0): prev=0, covariates[0]
    }
    const int hidx = tid - 448;   // head threads: [448,512)
    __syncthreads();

    // E-phase mapping: thread -> (row, 4 consecutive k)
    const int er = tid >> 4;
    const int ek = (tid & 15) * 4;

    for (int t = 0; t < Sq; t++){
        // ================= phase G: gates GEMM =================
        // prefetch x(t+1) early (hidden under GEMM)
        if (tid < RPB*12 && t+1 < Sq){
            if (xj == 0)       xreg = target[xb*Sq + t] * isc_s[xr];
            else if (xj <= 10) xreg = covar[(xb*Sq + t+1)*10 + (xj-1)];
        }

        ull acc[4][4];
        #pragma unroll
        for (int j = 0; j < 4; j++)
            #pragma unroll
            for (int g = 0; g < 4; g++) acc[j][g] = 0ull;

        // x part: 6 kk
        {
            const ulonglong2* wpi = (const ulonglong2*)wpi_s;
            #pragma unroll
            for (int kk = 0; kk < 6; kk++){
                ulonglong2 wa = wpi[(kk*256 + gbase) >> 1];
                ulonglong2 wb = wpi[(kk*256 + gbase + 2) >> 1];
                #pragma unroll
                for (int j = 0; j < 4; j++){
                    ull xv = *(const ull*)(x_s + (rA + 4*j)*12 + kk*2);
                    ffma2(acc[j][0], xv, wa.x);
                    ffma2(acc[j][1], xv, wa.y);
                    ffma2(acc[j][2], xv, wb.x);
                    ffma2(acc[j][3], xv, wb.y);
                }
            }
        }
        // h part: 32 kk, 2 kk per iteration
        {
            const float* hb = h2_s + ((t+1)&1)*HBUF;   // h(t-1)
            const ulonglong2* wph = (const ulonglong2*)wph_s;
            #pragma unroll 4
            for (int kk2 = 0; kk2 < 16; kk2++){
                ulonglong2 wa0 = wph[((2*kk2  )*256 + gbase    ) >> 1];
                ulonglong2 wb0 = wph[((2*kk2  )*256 + gbase + 2) >> 1];
                ulonglong2 wa1 = wph[((2*kk2+1)*256 + gbase    ) >> 1];
                ulonglong2 wb1 = wph[((2*kk2+1)*256 + gbase + 2) >> 1];
                #pragma unroll
                for (int j = 0; j < 4; j++){
                    ulonglong2 hv = *(const ulonglong2*)(hb + (rA + 4*j)*HSTR + kk2*4);
                    ffma2(acc[j][0], hv.x, wa0.x);
                    ffma2(acc[j][1], hv.x, wa0.y);
                    ffma2(acc[j][2], hv.x, wb0.x);
                    ffma2(acc[j][3], hv.x, wb0.y);
                    ffma2(acc[j][0], hv.y, wa1.x);
                    ffma2(acc[j][1], hv.y, wa1.y);
                    ffma2(acc[j][2], hv.y, wb1.x);
                    ffma2(acc[j][3], hv.y, wb1.y);
                }
            }
        }
        // epilogue: fold parity + pre, store gates
        #pragma unroll
        for (int j = 0; j < 4; j++){
            float4 p = *(const float4*)(pre_s + (rA + 4*j)*256 + gbase);
            float2 a0 = unpack2(acc[j][0]);
            float2 a1 = unpack2(acc[j][1]);
            float2 a2 = unpack2(acc[j][2]);
            float2 a3 = unpack2(acc[j][3]);
            float4 g;
            g.x = a0.x + a0.y + p.x;
            g.y = a1.x + a1.y + p.y;
            g.z = a2.x + a2.y + p.z;
            g.w = a3.x + a3.y + p.w;
            *(float4*)(gates_s + (rA + 4*j)*256 + gbase) = g;
        }
        __syncthreads();

        // ================= phase EWH: cell + x-write + head =================
        {
            const float* gr = gates_s + er*256;
            float4 gi4 = *(const float4*)(gr + ek);
            float4 gf4 = *(const float4*)(gr + 64 + ek);
            float4 gg4 = *(const float4*)(gr + 128 + ek);
            float4 go4 = *(const float4*)(gr + 192 + ek);
            float4 c4  = *(const float4*)(c_s + er*64 + ek);
            float4 h4;
            {
                float i0=sigf(gi4.x), f0=sigf(gf4.x), g0=tanh_f(gg4.x), o0=sigf(go4.x);
                c4.x = fmaf(f0, c4.x, i0*g0); h4.x = o0*tanh_f(c4.x);
                float i1=sigf(gi4.y), f1=sigf(gf4.y), g1=tanh_f(gg4.y), o1=sigf(go4.y);
                c4.y = fmaf(f1, c4.y, i1*g1); h4.y = o1*tanh_f(c4.y);
                float i2=sigf(gi4.z), f2=sigf(gf4.z), g2=tanh_f(gg4.z), o2=sigf(go4.z);
                c4.z = fmaf(f2, c4.z, i2*g2); h4.z = o2*tanh_f(c4.z);
                float i3=sigf(gi4.w), f3=sigf(gf4.w), g3=tanh_f(gg4.w), o3=sigf(go4.w);
                c4.w = fmaf(f3, c4.w, i3*g3); h4.w = o3*tanh_f(c4.w);
            }
            *(float4*)(c_s + er*64 + ek) = c4;
            *(float4*)(h2_s + (t&1)*HBUF + er*HSTR + ek) = h4;
        }
        if (tid < RPB*12){
            x_s[tid] = xreg;                         // x(t+1)
        } else if (hidx >= 0 && t > 0){
            // head for step t-1 reads h(t-1) in buffer (t-1)&1 (read-only this phase)
            int r = hidx >> 1, wsel = hidx & 1;
            const float* hr = h2_s + ((t-1)&1)*HBUF + r*HSTR;
            float a0=0.f,a1=0.f,a2=0.f,a3=0.f;
            #pragma unroll 8
            for (int k = 0; k < 64; k += 4){
                a0 = fmaf(hr[k],   wout_s[2*k     + wsel], a0);
                a1 = fmaf(hr[k+1], wout_s[2*(k+1) + wsel], a1);
                a2 = fmaf(hr[k+2], wout_s[2*(k+2) + wsel], a2);
                a3 = fmaf(hr[k+3], wout_s[2*(k+3) + wsel], a3);
            }
            float a = (a0+a1)+(a2+a3) + b_out[wsel];
            float sp = (a > 15.0f) ? a : log1pf(__expf(a));
            sp += 1e-4f;
            int b = row0 + r;
            if (wsel == 0) out[b*Sq + (t-1)] = sp * sc_s[r];
            else           out[Bq*Sq + b*Sq + (t-1)] = sp;
        }
        __syncthreads();
    }

    // final head for t = Sq-1 (h in buffer (Sq-1)&1)
    if (hidx >= 0){
        int r = hidx >> 1, wsel = hidx & 1;
        const float* hr = h2_s + ((Sq-1)&1)*HBUF + r*HSTR;
        float a0=0.f,a1=0.f,a2=0.f,a3=0.f;
        #pragma unroll 8
        for (int k = 0; k < 64; k += 4){
            a0 = fmaf(hr[k],   wout_s[2*k     + wsel], a0);
            a1 = fmaf(hr[k+1], wout_s[2*(k+1) + wsel], a1);
            a2 = fmaf(hr[k+2], wout_s[2*(k+2) + wsel], a2);
            a3 = fmaf(hr[k+3], wout_s[2*(k+3) + wsel], a3);
        }
        float a = (a0+a1)+(a2+a3) + b_out[wsel];
        float sp = (a > 15.0f) ? a : log1pf(__expf(a));
        sp += 1e-4f;
        int b = row0 + r;
        if (wsel == 0) out[b*Sq + (Sq-1)] = sp * sc_s[r];
        else           out[Bq*Sq + b*Sq + (Sq-1)] = sp;
    }
}

extern "C" void kernel_launch(void* const* d_in, const int* in_sizes, int n_in,
                              void* d_out, int out_size)
{
    (void)in_sizes; (void)n_in; (void)out_size;
    cudaFuncSetAttribute(deepar_kernel,
                         cudaFuncAttributeMaxDynamicSharedMemorySize, SMEM_BYTES);
    deepar_kernel<<<NB, NT, SMEM_BYTES>>>(
        (const float*)d_in[0],   // target
        (const float*)d_in[1],   // covariates
        (const int*)  d_in[2],   // static_cats
        (const float*)d_in[3],   // scale
        (const float*)d_in[4],   // emb0
        (const float*)d_in[5],   // emb1
        (const float*)d_in[6],   // emb2
        (const float*)d_in[7],   // emb3
        (const float*)d_in[8],   // w_ih
        (const float*)d_in[9],   // w_hh
        (const float*)d_in[10],  // bias
        (const float*)d_in[11],  // w_out
        (const float*)d_in[12],  // b_out
        (float*)d_out);
}

// round 4
// speedup vs baseline: 1.4592x; 1.4592x over previous
#include <cuda_runtime.h>
#include <math.h>

#define Bq 4096
#define Sq 512
#define NT 1024
#define NB 128
#define RPB 32
#define HSTR 80               // unified operand row: h[0:64] | x[64:76] | pad
#define HBUF (RPB*HSTR)       // 2560 floats per buffer

typedef unsigned long long ull;

// shared layout (float offsets)
#define O_WU    0                        // packed unified weights [38 kk][256 g] x2 = 19456
#define O_PRE   (O_WU + 19456)           // pre [32][256]     = 8192
#define O_GATE  (O_PRE + 8192)           // gates upper+pre   = 8192
#define O_SCR   (O_GATE + 8192)          // scratch lower     = 8192
#define O_H2    (O_SCR + 8192)           // 2 * [32][HSTR]    = 5120
#define O_C     (O_H2 + 2*HBUF)          // c [32][64]        = 2048
#define O_WOUT  (O_C + 2048)             // 128
#define O_SC    (O_WOUT + 128)
#define O_ISC   (O_SC + 32)
#define SM_TOTAL (O_ISC + 32)
#define SMEM_BYTES (SM_TOTAL*4)          // ~205.6 KB

__device__ __forceinline__ float sigf(float x){ return 1.0f/(1.0f+__expf(-x)); }
__device__ __forceinline__ float tanh_f(float x){ return 2.0f/(1.0f+__expf(-2.0f*x)) - 1.0f; }

__device__ __forceinline__ void ffma2(ull &d, ull a, ull b){
    asm("fma.rn.f32x2 %0, %1, %2, %0;" : "+l"(d) : "l"(a), "l"(b));
}
__device__ __forceinline__ float2 unpack2(ull v){
    float2 f; asm("mov.b64 {%0,%1}, %2;" : "=f"(f.x), "=f"(f.y) : "l"(v)); return f;
}

__global__ void __launch_bounds__(NT,1)
deepar_kernel(const float* __restrict__ target,
              const float* __restrict__ covar,
              const int*   __restrict__ cats,
              const float* __restrict__ scale,
              const float* __restrict__ e0,
              const float* __restrict__ e1,
              const float* __restrict__ e2,
              const float* __restrict__ e3,
              const float* __restrict__ w_ih,
              const float* __restrict__ w_hh,
              const float* __restrict__ bias,
              const float* __restrict__ w_out,
              const float* __restrict__ b_out,
              float* __restrict__ out)
{
    extern __shared__ float sm[];
    float* wu_s    = sm + O_WU;
    float* pre_s   = sm + O_PRE;
    float* gates_s = sm + O_GATE;
    float* scr_s   = sm + O_SCR;
    float* h2_s    = sm + O_H2;
    float* c_s     = sm + O_C;
    float* wout_s  = sm + O_WOUT;
    float* sc_s    = sm + O_SC;
    float* isc_s   = sm + O_ISC;
    float* sx_s    = gates_s;          // alias: static_x [32][66], pre-loop only

    const int tid  = threadIdx.x;
    const int row0 = blockIdx.x * RPB;

    // ---- pack unified weights [h(64) | prev,cov(11), zero] k-pair packed ----
    for (int i = tid; i < 38*256; i += NT){
        int kk = i >> 8, g = i & 255;
        int k0 = 2*kk, k1 = 2*kk + 1;
        float v0 = (k0 < 64) ? w_hh[k0*256 + g] : ((k0 < 75) ? w_ih[(k0-64)*256 + g] : 0.0f);
        float v1 = (k1 < 64) ? w_hh[k1*256 + g] : ((k1 < 75) ? w_ih[(k1-64)*256 + g] : 0.0f);
        wu_s[2*i]   = v0;
        wu_s[2*i+1] = v1;
    }
    if (tid < 128) wout_s[tid] = w_out[tid];
    if (tid < RPB){
        float s = scale[row0 + tid];
        sc_s[tid]  = s;
        isc_s[tid] = 1.0f / fmaxf(s, 1e-4f);
    }
    for (int i = tid; i < 2*HBUF; i += NT) h2_s[i] = 0.0f;
    for (int i = tid; i < RPB*64; i += NT) c_s[i] = 0.0f;

    // ---- static_x staging into sx_s[32][66] ----
    for (int e = tid; e < RPB*65; e += NT){
        int r = e / 65, j = e - r*65;
        int b = row0 + r;
        float v;
        if (j < 64){
            int tsel = j >> 4, jj = j & 15;
            int c = cats[b*4 + tsel];
            const float* et = (tsel==0)?e0:(tsel==1)?e1:(tsel==2)?e2:e3;
            v = et[c*16 + jj];
        } else {
            v = log1pf(scale[b]);
        }
        sx_s[r*66 + j] = v;
    }
    __syncthreads();

    // ---- precompute pre = bias + static_x @ w_ih[11:76] (1024 thr: 2 rows x 4 gates) ----
    {
        const int ptx = tid & 63;          // gates 4*ptx..+3
        const int pty = tid >> 6;          // rows 2*pty..+1
        float accp[2][4];
        float4 bv = *(const float4*)(bias + 4*ptx);
        #pragma unroll
        for (int j = 0; j < 2; j++){
            accp[j][0]=bv.x; accp[j][1]=bv.y; accp[j][2]=bv.z; accp[j][3]=bv.w;
        }
        for (int k = 0; k < 65; k++){
            float4 w = *(const float4*)(w_ih + (11+k)*256 + 4*ptx);
            #pragma unroll
            for (int j = 0; j < 2; j++){
                float xv = sx_s[(2*pty + j)*66 + k];
                accp[j][0] = fmaf(xv, w.x, accp[j][0]);
                accp[j][1] = fmaf(xv, w.y, accp[j][1]);
                accp[j][2] = fmaf(xv, w.z, accp[j][2]);
                accp[j][3] = fmaf(xv, w.w, accp[j][3]);
            }
        }
        #pragma unroll
        for (int j = 0; j < 2; j++){
            float4 p; p.x=accp[j][0]; p.y=accp[j][1]; p.z=accp[j][2]; p.w=accp[j][3];
            *(float4*)(pre_s + (2*pty + j)*256 + 4*ptx) = p;
        }
    }

    // ---- x(0) into buffer 1 (G(0) reads hb[(0+1)&1]) ----
    int xr = 0, xj = 0, xb = 0;
    float xreg = 0.0f;
    if (tid < RPB*12){
        xr = tid / 12; xj = tid - xr*12; xb = row0 + xr;
        float v = 0.0f;
        if (xj >= 1 && xj <= 10) v = covar[(xb*Sq + 0)*10 + (xj-1)];
        h2_s[1*HBUF + xr*HSTR + 64 + xj] = v;
    }
    __syncthreads();   // pre/sx readers done; gates_s reusable

    // ---- G mapping ----
    const int tx    = tid & 127;        // gate-pair: gates 2tx, 2tx+1
    const int ty    = (tid >> 7) & 3;   // row-group
    const int kh    = tid >> 9;         // k-half: 0 -> kk2 0..9, 1 -> kk2 10..18
    const int rbase = ty * 8;
    // ---- E mapping ----
    const int er  = tid >> 5;           // row (warp-uniform)
    const int ek2 = (tid & 31) * 2;     // 2 k per thread
    const int hidx = tid - (NT - 64);   // head threads: last 64

    const ulonglong2* wu2 = (const ulonglong2*)wu_s;

    for (int t = 0; t < Sq; t++){
        // prefetch x(t+1)
        if (tid < RPB*12 && t+1 < Sq){
            if (xj == 0)       xreg = target[xb*Sq + t] * isc_s[xr];
            else if (xj <= 10) xreg = covar[(xb*Sq + t+1)*10 + (xj-1)];
            else               xreg = 0.0f;
        }

        const float* hb = h2_s + ((t+1)&1)*HBUF;    // h(t-1) | x(t)
        ull acc[8][2];
        #pragma unroll
        for (int j = 0; j < 8; j++){ acc[j][0]=0ull; acc[j][1]=0ull; }

        if (kh == 0){
            #pragma unroll
            for (int kk2 = 0; kk2 < 10; kk2++){
                ulonglong2 wA = wu2[(2*kk2  )*128 + tx];
                ulonglong2 wB = wu2[(2*kk2+1)*128 + tx];
                #pragma unroll
                for (int j = 0; j < 8; j++){
                    ulonglong2 hv = *(const ulonglong2*)(hb + (rbase+j)*HSTR + kk2*4);
                    ffma2(acc[j][0], hv.x, wA.x);
                    ffma2(acc[j][1], hv.x, wA.y);
                    ffma2(acc[j][0], hv.y, wB.x);
                    ffma2(acc[j][1], hv.y, wB.y);
                }
            }
            // store lower partial (fold parity)
            #pragma unroll
            for (int j = 0; j < 8; j++){
                float2 a0 = unpack2(acc[j][0]);
                float2 a1 = unpack2(acc[j][1]);
                *(float2*)(scr_s + (rbase+j)*256 + 2*tx) =
                    make_float2(a0.x + a0.y, a1.x + a1.y);
            }
        } else {
            #pragma unroll
            for (int kk2 = 10; kk2 < 19; kk2++){
                ulonglong2 wA = wu2[(2*kk2  )*128 + tx];
                ulonglong2 wB = wu2[(2*kk2+1)*128 + tx];
                #pragma unroll
                for (int j = 0; j < 8; j++){
                    ulonglong2 hv = *(const ulonglong2*)(hb + (rbase+j)*HSTR + kk2*4);
                    ffma2(acc[j][0], hv.x, wA.x);
                    ffma2(acc[j][1], hv.x, wA.y);
                    ffma2(acc[j][0], hv.y, wB.x);
                    ffma2(acc[j][1], hv.y, wB.y);
                }
            }
            // store upper partial + pre
            #pragma unroll
            for (int j = 0; j < 8; j++){
                float2 p  = *(const float2*)(pre_s + (rbase+j)*256 + 2*tx);
                float2 a0 = unpack2(acc[j][0]);
                float2 a1 = unpack2(acc[j][1]);
                *(float2*)(gates_s + (rbase+j)*256 + 2*tx) =
                    make_float2(a0.x + a0.y + p.x, a1.x + a1.y + p.y);
            }
        }
        __syncthreads();

        // ================= phase E: combine + cell + x-write + head =================
        {
            float* hw = h2_s + (t&1)*HBUF;
            const float* gl = gates_s + er*256;
            const float* sl = scr_s + er*256;
            float2 gi = *(const float2*)(gl + ek2);
            float2 si = *(const float2*)(sl + ek2);
            float2 gf = *(const float2*)(gl + 64 + ek2);
            float2 sf = *(const float2*)(sl + 64 + ek2);
            float2 gg = *(const float2*)(gl + 128 + ek2);
            float2 sg = *(const float2*)(sl + 128 + ek2);
            float2 go = *(const float2*)(gl + 192 + ek2);
            float2 so = *(const float2*)(sl + 192 + ek2);
            float2 c2 = *(const float2*)(c_s + er*64 + ek2);
            float i0 = sigf(gi.x + si.x), i1 = sigf(gi.y + si.y);
            float f0 = sigf(gf.x + sf.x), f1 = sigf(gf.y + sf.y);
            float g0 = tanh_f(gg.x + sg.x), g1 = tanh_f(gg.y + sg.y);
            float o0 = sigf(go.x + so.x), o1 = sigf(go.y + so.y);
            c2.x = fmaf(f0, c2.x, i0*g0);
            c2.y = fmaf(f1, c2.y, i1*g1);
            *(float2*)(c_s + er*64 + ek2) = c2;
            *(float2*)(hw + er*HSTR + ek2) = make_float2(o0*tanh_f(c2.x), o1*tanh_f(c2.y));
        }
        if (tid < RPB*12){
            h2_s[(t&1)*HBUF + xr*HSTR + 64 + xj] = xreg;    // x(t+1)
        }
        if (hidx >= 0 && t > 0){
            // head for step t-1: h(t-1) lives in buffer (t+1)&1 (stable this phase)
            int r = hidx >> 1, wsel = hidx & 1;
            const float* hr = h2_s + ((t+1)&1)*HBUF + r*HSTR;
            float a0=0.f,a1=0.f,a2=0.f,a3=0.f;
            #pragma unroll 8
            for (int k = 0; k < 64; k += 4){
                a0 = fmaf(hr[k],   wout_s[2*k     + wsel], a0);
                a1 = fmaf(hr[k+1], wout_s[2*(k+1) + wsel], a1);
                a2 = fmaf(hr[k+2], wout_s[2*(k+2) + wsel], a2);
                a3 = fmaf(hr[k+3], wout_s[2*(k+3) + wsel], a3);
            }
            float a = (a0+a1)+(a2+a3) + b_out[wsel];
            float sp = (a > 15.0f) ? a : log1pf(__expf(a));
            sp += 1e-4f;
            int b = row0 + r;
            if (wsel == 0) out[b*Sq + (t-1)] = sp * sc_s[r];
            else           out[Bq*Sq + b*Sq + (t-1)] = sp;
        }
        __syncthreads();
    }

    // final head for t = Sq-1 : h in buffer (Sq-1)&1
    if (hidx >= 0){
        int r = hidx >> 1, wsel = hidx & 1;
        const float* hr = h2_s + ((Sq-1)&1)*HBUF + r*HSTR;
        float a0=0.f,a1=0.f,a2=0.f,a3=0.f;
        #pragma unroll 8
        for (int k = 0; k < 64; k += 4){
            a0 = fmaf(hr[k],   wout_s[2*k     + wsel], a0);
            a1 = fmaf(hr[k+1], wout_s[2*(k+1) + wsel], a1);
            a2 = fmaf(hr[k+2], wout_s[2*(k+2) + wsel], a2);
            a3 = fmaf(hr[k+3], wout_s[2*(k+3) + wsel], a3);
        }
        float a = (a0+a1)+(a2+a3) + b_out[wsel];
        float sp = (a > 15.0f) ? a : log1pf(__expf(a));
        sp += 1e-4f;
        int b = row0 + r;
        if (wsel == 0) out[b*Sq + (Sq-1)] = sp * sc_s[r];
        else           out[Bq*Sq + b*Sq + (Sq-1)] = sp;
    }
}

extern "C" void kernel_launch(void* const* d_in, const int* in_sizes, int n_in,
                              void* d_out, int out_size)
{
    (void)in_sizes; (void)n_in; (void)out_size;
    cudaFuncSetAttribute(deepar_kernel,
                         cudaFuncAttributeMaxDynamicSharedMemorySize, SMEM_BYTES);
    deepar_kernel<<<NB, NT, SMEM_BYTES>>>(
        (const float*)d_in[0],   // target
        (const float*)d_in[1],   // covariates
        (const int*)  d_in[2],   // static_cats
        (const float*)d_in[3],   // scale
        (const float*)d_in[4],   // emb0
        (const float*)d_in[5],   // emb1
        (const float*)d_in[6],   // emb2
        (const float*)d_in[7],   // emb3
        (const float*)d_in[8],   // w_ih
        (const float*)d_in[9],   // w_hh
        (const float*)d_in[10],  // bias
        (const float*)d_in[11],  // w_out
        (const float*)d_in[12],  // b_out
        (float*)d_out);
}

// round 5
// speedup vs baseline: 1.5904x; 1.0899x over previous
#include <cuda_runtime.h>
#include <math.h>

#define Bq 4096
#define Sq 512
#define NT 512
#define NB 128
#define RPB 32
#define KST 76               // unified k stride: h[0:64) | x[64:75) | pad
#define HBUFSZ (RPB*KST)     // 2432 floats per h|x buffer

typedef unsigned long long ull;

// shared layout (float offsets)
#define O_WA   0                         // wa [38 kk][64 g~] float4 = 9728
#define O_WB   (O_WA + 38*64*4)          // wb same                  = 9728
#define O_HB   (O_WB + 38*64*4)          // 2 * [32][KST]            = 4864
#define O_WOUT (O_HB + 2*HBUFSZ)         // 128
#define O_SC   (O_WOUT + 128)
#define O_ISC  (O_SC + 32)
#define SM_TOTAL (O_ISC + 32)
#define SMEM_BYTES (SM_TOTAL*4)          // ~98 KB

__device__ __forceinline__ float sigf(float x){ return 1.0f/(1.0f+__expf(-x)); }
__device__ __forceinline__ float tanh_f(float x){ return 2.0f/(1.0f+__expf(-2.0f*x)) - 1.0f; }

__device__ __forceinline__ void ffma2(ull &d, ull a, ull b){
    asm("fma.rn.f32x2 %0, %1, %2, %0;" : "+l"(d) : "l"(a), "l"(b));
}
__device__ __forceinline__ float fold2(ull v){
    float2 f; asm("mov.b64 {%0,%1}, %2;" : "=f"(f.x), "=f"(f.y) : "l"(v));
    return f.x + f.y;
}

__global__ void __launch_bounds__(NT,1)
deepar_kernel(const float* __restrict__ target,
              const float* __restrict__ covar,
              const int*   __restrict__ cats,
              const float* __restrict__ scale,
              const float* __restrict__ e0,
              const float* __restrict__ e1,
              const float* __restrict__ e2,
              const float* __restrict__ e3,
              const float* __restrict__ w_ih,
              const float* __restrict__ w_hh,
              const float* __restrict__ bias,
              const float* __restrict__ w_out,
              const float* __restrict__ b_out,
              float* __restrict__ out)
{
    extern __shared__ float sm[];
    float* wa_s   = sm + O_WA;
    float* wb_s   = sm + O_WB;
    float* hbuf   = sm + O_HB;
    float* wout_s = sm + O_WOUT;
    float* sc_s   = sm + O_SC;
    float* isc_s  = sm + O_ISC;
    float* sx_s   = sm + O_WA;     // alias: static_x [32][66], pre-phase only

    const int tid  = threadIdx.x;
    const int row0 = blockIdx.x * RPB;

    // ---- phase 0: stage static_x into sx_s (aliases wa_s; weights packed later) ----
    for (int e = tid; e < RPB*65; e += NT){
        int r = e / 65, j = e - r*65;
        int b = row0 + r;
        float v;
        if (j < 64){
            int tsel = j >> 4, jj = j & 15;
            int c = cats[b*4 + tsel];
            const float* et = (tsel==0)?e0:(tsel==1)?e1:(tsel==2)?e2:e3;
            v = et[c*16 + jj];
        } else {
            v = log1pf(scale[b]);
        }
        sx_s[r*66 + j] = v;
    }
    __syncthreads();

    // ---- thread mapping: g~ = tid&63 (cell col), rg = tid>>6 (4-row group) ----
    const int gt    = tid & 63;
    const int rg    = tid >> 6;
    const int rbase = rg * 4;

    // ---- pre[j][tp] = bias + static_x @ w_ih[11:76], in registers ----
    float pre[4][4];
    {
        #pragma unroll
        for (int tp = 0; tp < 4; tp++){
            float bv = bias[tp*64 + gt];
            #pragma unroll
            for (int j = 0; j < 4; j++) pre[j][tp] = bv;
        }
        for (int k = 0; k < 65; k++){
            const float* wr = w_ih + (11+k)*256 + gt;
            float w0 = wr[0], w1 = wr[64], w2 = wr[128], w3 = wr[192];
            #pragma unroll
            for (int j = 0; j < 4; j++){
                float xv = sx_s[(rbase+j)*66 + k];
                pre[j][0] = fmaf(xv, w0, pre[j][0]);
                pre[j][1] = fmaf(xv, w1, pre[j][1]);
                pre[j][2] = fmaf(xv, w2, pre[j][2]);
                pre[j][3] = fmaf(xv, w3, pre[j][3]);
            }
        }
    }
    __syncthreads();   // sx readers done; wa_s can be overwritten

    // ---- pack weights: wa[kk][g~] = {i:kpair, f:kpair}, wb = {g:kpair, o:kpair} ----
    for (int idx = tid; idx < 38*64; idx += NT){
        int kk = idx >> 6, g = idx & 63;
        int k0 = 2*kk, k1 = 2*kk + 1;
        #define WK(k,c) ((k) < 64 ? w_hh[(k)*256 + (c)] : ((k) < 75 ? w_ih[((k)-64)*256 + (c)] : 0.0f))
        float4 a4, b4;
        a4.x = WK(k0, gt*0 + g);       a4.y = WK(k1, g);
        a4.z = WK(k0, 64 + g);         a4.w = WK(k1, 64 + g);
        b4.x = WK(k0, 128 + g);        b4.y = WK(k1, 128 + g);
        b4.z = WK(k0, 192 + g);        b4.w = WK(k1, 192 + g);
        #undef WK
        *(float4*)(wa_s + idx*4) = a4;
        *(float4*)(wb_s + idx*4) = b4;
    }
    if (tid < 128) wout_s[tid] = w_out[tid];
    if (tid < RPB){
        float s = scale[row0 + tid];
        sc_s[tid]  = s;
        isc_s[tid] = 1.0f / fmaxf(s, 1e-4f);
    }
    for (int i = tid; i < 2*HBUFSZ; i += NT) hbuf[i] = 0.0f;
    __syncthreads();

    // ---- x(0) into hbuf[1] (GEMM(0) reads hbuf[(0+1)&1]) ----
    int xr = 0, xj = 0, xb = 0;
    float xreg = 0.0f;
    if (tid < RPB*12){
        xr = tid / 12; xj = tid - xr*12; xb = row0 + xr;
        float v = 0.0f;
        if (xj >= 1 && xj <= 10) v = covar[(xb*Sq + 0)*10 + (xj-1)];
        hbuf[1*HBUFSZ + xr*KST + 64 + xj] = v;
    }
    const int hidx = tid - 448;   // head threads: warps 14,15
    __syncthreads();

    float creg[4] = {0.0f, 0.0f, 0.0f, 0.0f};

    for (int t = 0; t < Sq; t++){
        const float* hb = hbuf + ((t+1)&1)*HBUFSZ;   // h(t-1) | x(t)

        // head for step t-1 on warps 14,15 (reads stable hb buffer)
        if (hidx >= 0 && t > 0){
            int r = hidx >> 1, wsel = hidx & 1;
            const float* hr = hb + r*KST;
            float a0=0.f,a1=0.f,a2=0.f,a3=0.f;
            #pragma unroll 8
            for (int k = 0; k < 64; k += 4){
                a0 = fmaf(hr[k],   wout_s[2*k     + wsel], a0);
                a1 = fmaf(hr[k+1], wout_s[2*(k+1) + wsel], a1);
                a2 = fmaf(hr[k+2], wout_s[2*(k+2) + wsel], a2);
                a3 = fmaf(hr[k+3], wout_s[2*(k+3) + wsel], a3);
            }
            float a = (a0+a1)+(a2+a3) + b_out[wsel];
            float sp = (a > 15.0f) ? a : log1pf(__expf(a));
            sp += 1e-4f;
            int b = row0 + r;
            if (wsel == 0) out[b*Sq + (t-1)] = sp * sc_s[r];
            else           out[Bq*Sq + b*Sq + (t-1)] = sp;
        }
        // prefetch x(t+1) (latency hidden under GEMM)
        if (tid < RPB*12 && t+1 < Sq){
            if (xj == 0)       xreg = target[xb*Sq + t] * isc_s[xr];
            else if (xj <= 10) xreg = covar[(xb*Sq + t+1)*10 + (xj-1)];
            else               xreg = 0.0f;
        }

        // ================= GEMM: all 4 gate types for (4 rows x g~) =================
        ull acc[4][4];
        #pragma unroll
        for (int j = 0; j < 4; j++)
            #pragma unroll
            for (int tp = 0; tp < 4; tp++) acc[j][tp] = 0ull;

        #pragma unroll
        for (int kk2 = 0; kk2 < 19; kk2++){
            ulonglong2 wa0 = *(const ulonglong2*)(wa_s + ((2*kk2  )*64 + gt)*4);
            ulonglong2 wb0 = *(const ulonglong2*)(wb_s + ((2*kk2  )*64 + gt)*4);
            ulonglong2 wa1 = *(const ulonglong2*)(wa_s + ((2*kk2+1)*64 + gt)*4);
            ulonglong2 wb1 = *(const ulonglong2*)(wb_s + ((2*kk2+1)*64 + gt)*4);
            #pragma unroll
            for (int j = 0; j < 4; j++){
                ulonglong2 hv = *(const ulonglong2*)(hb + (rbase+j)*KST + kk2*4);
                ffma2(acc[j][0], hv.x, wa0.x);
                ffma2(acc[j][1], hv.x, wa0.y);
                ffma2(acc[j][2], hv.x, wb0.x);
                ffma2(acc[j][3], hv.x, wb0.y);
                ffma2(acc[j][0], hv.y, wa1.x);
                ffma2(acc[j][1], hv.y, wa1.y);
                ffma2(acc[j][2], hv.y, wb1.x);
                ffma2(acc[j][3], hv.y, wb1.y);
            }
        }

        // ================= fused LSTM cell (registers) + h store =================
        {
            float* hw = hbuf + (t&1)*HBUFSZ;
            #pragma unroll
            for (int j = 0; j < 4; j++){
                float gi = fold2(acc[j][0]) + pre[j][0];
                float gf = fold2(acc[j][1]) + pre[j][1];
                float gg = fold2(acc[j][2]) + pre[j][2];
                float go = fold2(acc[j][3]) + pre[j][3];
                float i = sigf(gi);
                float f = sigf(gf);
                float g = tanh_f(gg);
                float o = sigf(go);
                float c = fmaf(f, creg[j], i*g);
                creg[j] = c;
                hw[(rbase+j)*KST + gt] = o * tanh_f(c);
            }
        }
        if (tid < RPB*12){
            hbuf[(t&1)*HBUFSZ + xr*KST + 64 + xj] = xreg;   // x(t+1)
        }
        __syncthreads();
    }

    // final head for t = Sq-1 (h in hbuf[(Sq-1)&1])
    if (hidx >= 0){
        int r = hidx >> 1, wsel = hidx & 1;
        const float* hr = hbuf + ((Sq-1)&1)*HBUFSZ + r*KST;
        float a0=0.f,a1=0.f,a2=0.f,a3=0.f;
        #pragma unroll 8
        for (int k = 0; k < 64; k += 4){
            a0 = fmaf(hr[k],   wout_s[2*k     + wsel], a0);
            a1 = fmaf(hr[k+1], wout_s[2*(k+1) + wsel], a1);
            a2 = fmaf(hr[k+2], wout_s[2*(k+2) + wsel], a2);
            a3 = fmaf(hr[k+3], wout_s[2*(k+3) + wsel], a3);
        }
        float a = (a0+a1)+(a2+a3) + b_out[wsel];
        float sp = (a > 15.0f) ? a : log1pf(__expf(a));
        sp += 1e-4f;
        int b = row0 + r;
        if (wsel == 0) out[b*Sq + (Sq-1)] = sp * sc_s[r];
        else           out[Bq*Sq + b*Sq + (Sq-1)] = sp;
    }
}

extern "C" void kernel_launch(void* const* d_in, const int* in_sizes, int n_in,
                              void* d_out, int out_size)
{
    (void)in_sizes; (void)n_in; (void)out_size;
    cudaFuncSetAttribute(deepar_kernel,
                         cudaFuncAttributeMaxDynamicSharedMemorySize, SMEM_BYTES);
    deepar_kernel<<<NB, NT, SMEM_BYTES>>>(
        (const float*)d_in[0],   // target
        (const float*)d_in[1],   // covariates
        (const int*)  d_in[2],   // static_cats
        (const float*)d_in[3],   // scale
        (const float*)d_in[4],   // emb0
        (const float*)d_in[5],   // emb1
        (const float*)d_in[6],   // emb2
        (const float*)d_in[7],   // emb3
        (const float*)d_in[8],   // w_ih
        (const float*)d_in[9],   // w_hh
        (const float*)d_in[10],  // bias
        (const float*)d_in[11],  // w_out
        (const float*)d_in[12],  // b_out
        (float*)d_out);
}

// round 7
// speedup vs baseline: 1.7871x; 1.1236x over previous
#include <cuda_runtime.h>
#include <math.h>

#define Bq 4096
#define Sq 512
#define NT 512
#define NB 128
#define RPB 32
#define KST 76               // unified k stride: h[0:64) | x[64:75) | pad
#define HBUFSZ (RPB*KST)     // 2432 floats per h|x buffer

typedef unsigned long long ull;

// shared layout (float offsets)
#define O_WA   0                         // wa [38 kk][64 g~] float4 = 9728
#define O_WB   (O_WA + 38*64*4)          // wb same                  = 9728
#define O_HB   (O_WB + 38*64*4)          // 2 * [32][KST]            = 4864
#define O_WOUT (O_HB + 2*HBUFSZ)         // 128
#define O_SC   (O_WOUT + 128)
#define O_ISC  (O_SC + 32)
#define SM_TOTAL (O_ISC + 32)
#define SMEM_BYTES (SM_TOTAL*4)          // ~98 KB

__device__ __forceinline__ float sigf(float x){ return 1.0f/(1.0f+__expf(-x)); }
__device__ __forceinline__ float tanh_f(float x){ return 2.0f/(1.0f+__expf(-2.0f*x)) - 1.0f; }

__device__ __forceinline__ void ffma2(ull &d, ull a, ull b){
    asm("fma.rn.f32x2 %0, %1, %2, %0;" : "+l"(d) : "l"(a), "l"(b));
}
__device__ __forceinline__ float fold2(ull v){
    float2 f; asm("mov.b64 {%0,%1}, %2;" : "=f"(f.x), "=f"(f.y) : "l"(v));
    return f.x + f.y;
}
__device__ __forceinline__ void pbar(int id){
    asm volatile("bar.sync %0, 64;" :: "r"(id) : "memory");
}

__global__ void __launch_bounds__(NT,1)
deepar_kernel(const float* __restrict__ target,
              const float* __restrict__ covar,
              const int*   __restrict__ cats,
              const float* __restrict__ scale,
              const float* __restrict__ e0,
              const float* __restrict__ e1,
              const float* __restrict__ e2,
              const float* __restrict__ e3,
              const float* __restrict__ w_ih,
              const float* __restrict__ w_hh,
              const float* __restrict__ bias,
              const float* __restrict__ w_out,
              const float* __restrict__ b_out,
              float* __restrict__ out)
{
    extern __shared__ float sm[];
    float* wa_s   = sm + O_WA;
    float* wb_s   = sm + O_WB;
    float* hbuf   = sm + O_HB;
    float* wout_s = sm + O_WOUT;
    float* sc_s   = sm + O_SC;
    float* isc_s  = sm + O_ISC;
    float* sx_s   = sm + O_WA;     // alias: static_x [32][66], pre-phase only

    const int tid  = threadIdx.x;
    const int row0 = blockIdx.x * RPB;

    // ---- phase 0: stage static_x into sx_s (aliases wa_s; weights packed later) ----
    for (int e = tid; e < RPB*65; e += NT){
        int r = e / 65, j = e - r*65;
        int b = row0 + r;
        float v;
        if (j < 64){
            int tsel = j >> 4, jj = j & 15;
            int c = cats[b*4 + tsel];
            const float* et = (tsel==0)?e0:(tsel==1)?e1:(tsel==2)?e2:e3;
            v = et[c*16 + jj];
        } else {
            v = log1pf(scale[b]);
        }
        sx_s[r*66 + j] = v;
    }
    __syncthreads();

    // ---- thread mapping: g~ = tid&63, pair p = tid>>6 owns rows 4p..4p+3 ----
    const int gt    = tid & 63;
    const int pid   = tid >> 6;        // 0..7
    const int rbase = pid * 4;
    const int wInPair = (tid >> 5) & 1;
    const int lane  = tid & 31;
    const int pairLane = wInPair*32 + lane;   // 0..63 within pair

    // ---- pre[j][tp] = bias + static_x @ w_ih[11:76], in registers ----
    float pre[4][4];
    {
        #pragma unroll
        for (int tp = 0; tp < 4; tp++){
            float bv = bias[tp*64 + gt];
            #pragma unroll
            for (int j = 0; j < 4; j++) pre[j][tp] = bv;
        }
        for (int k = 0; k < 65; k++){
            const float* wr = w_ih + (11+k)*256 + gt;
            float w0 = wr[0], w1 = wr[64], w2 = wr[128], w3 = wr[192];
            #pragma unroll
            for (int j = 0; j < 4; j++){
                float xv = sx_s[(rbase+j)*66 + k];
                pre[j][0] = fmaf(xv, w0, pre[j][0]);
                pre[j][1] = fmaf(xv, w1, pre[j][1]);
                pre[j][2] = fmaf(xv, w2, pre[j][2]);
                pre[j][3] = fmaf(xv, w3, pre[j][3]);
            }
        }
    }
    __syncthreads();   // sx readers done; wa_s can be overwritten

    // ---- pack weights: wa[kk][g~] = {i:kpair, f:kpair}, wb = {g:kpair, o:kpair} ----
    for (int idx = tid; idx < 38*64; idx += NT){
        int kk = idx >> 6, g = idx & 63;
        int k0 = 2*kk, k1 = 2*kk + 1;
        #define WK(k,c) ((k) < 64 ? w_hh[(k)*256 + (c)] : ((k) < 75 ? w_ih[((k)-64)*256 + (c)] : 0.0f))
        float4 a4, b4;
        a4.x = WK(k0, g);        a4.y = WK(k1, g);
        a4.z = WK(k0, 64 + g);   a4.w = WK(k1, 64 + g);
        b4.x = WK(k0, 128 + g);  b4.y = WK(k1, 128 + g);
        b4.z = WK(k0, 192 + g);  b4.w = WK(k1, 192 + g);
        #undef WK
        *(float4*)(wa_s + idx*4) = a4;
        *(float4*)(wb_s + idx*4) = b4;
    }
    if (tid < 128) wout_s[tid] = w_out[tid];
    if (tid < RPB){
        float s = scale[row0 + tid];
        sc_s[tid]  = s;
        isc_s[tid] = 1.0f / fmaxf(s, 1e-4f);
    }
    for (int i = tid; i < 2*HBUFSZ; i += NT) hbuf[i] = 0.0f;
    __syncthreads();

    // ---- per-pair x ownership: pairLane 0..47 cover (4 rows x 12 j) ----
    int xrow = 0, xj = 0, xb = 0;
    const bool xown = (pairLane < 48);
    float xreg = 0.0f;
    if (xown){
        xrow = rbase + (pairLane / 12);
        xj   = pairLane % 12;
        xb   = row0 + xrow;
        float v = 0.0f;
        if (xj >= 1 && xj <= 10) v = covar[(xb*Sq + 0)*10 + (xj-1)];
        hbuf[1*HBUFSZ + xrow*KST + 64 + xj] = v;   // x(0): prev=0, cov(0)
    }
    // head ownership: warp1-of-pair lanes 0..7 -> (4 rows x 2 outputs)
    const bool hown = (wInPair == 1) && (lane < 8);
    const int  hr_  = rbase + (lane >> 1);
    const int  hws  = lane & 1;
    __syncthreads();

    const int barid = pid + 1;
    float creg[4] = {0.0f, 0.0f, 0.0f, 0.0f};

    for (int t = 0; t < Sq; t++){
        pbar(barid);   // pair-local: h(t-1)/x(t) of rows rbase..rbase+3 are visible
        const float* hb = hbuf + ((t+1)&1)*HBUFSZ;   // h(t-1) | x(t)

        // head for step t-1 (reads stable hb rows of this pair)
        if (hown && t > 0){
            const float* hr = hb + hr_*KST;
            float a0=0.f,a1=0.f,a2=0.f,a3=0.f;
            #pragma unroll 8
            for (int k = 0; k < 64; k += 4){
                a0 = fmaf(hr[k],   wout_s[2*k     + hws], a0);
                a1 = fmaf(hr[k+1], wout_s[2*(k+1) + hws], a1);
                a2 = fmaf(hr[k+2], wout_s[2*(k+2) + hws], a2);
                a3 = fmaf(hr[k+3], wout_s[2*(k+3) + hws], a3);
            }
            float a = (a0+a1)+(a2+a3) + b_out[hws];
            float sp = (a > 15.0f) ? a : log1pf(__expf(a));
            sp += 1e-4f;
            int b = row0 + hr_;
            if (hws == 0) out[b*Sq + (t-1)] = sp * sc_s[hr_];
            else          out[Bq*Sq + b*Sq + (t-1)] = sp;
        }
        // prefetch x(t+1)
        if (xown && t+1 < Sq){
            if (xj == 0)       xreg = target[xb*Sq + t] * isc_s[xrow];
            else if (xj <= 10) xreg = covar[(xb*Sq + t+1)*10 + (xj-1)];
            else               xreg = 0.0f;
        }

        // ================= GEMM: all 4 gate types for (4 rows x g~) =================
        ull acc[4][4];
        #pragma unroll
        for (int j = 0; j < 4; j++)
            #pragma unroll
            for (int tp = 0; tp < 4; tp++) acc[j][tp] = 0ull;

        #pragma unroll
        for (int kk2 = 0; kk2 < 19; kk2++){
            ulonglong2 wa0 = *(const ulonglong2*)(wa_s + ((2*kk2  )*64 + gt)*4);
            ulonglong2 wb0 = *(const ulonglong2*)(wb_s + ((2*kk2  )*64 + gt)*4);
            ulonglong2 wa1 = *(const ulonglong2*)(wa_s + ((2*kk2+1)*64 + gt)*4);
            ulonglong2 wb1 = *(const ulonglong2*)(wb_s + ((2*kk2+1)*64 + gt)*4);
            #pragma unroll
            for (int j = 0; j < 4; j++){
                ulonglong2 hv = *(const ulonglong2*)(hb + (rbase+j)*KST + kk2*4);
                ffma2(acc[j][0], hv.x, wa0.x);
                ffma2(acc[j][1], hv.x, wa0.y);
                ffma2(acc[j][2], hv.x, wb0.x);
                ffma2(acc[j][3], hv.x, wb0.y);
                ffma2(acc[j][0], hv.y, wa1.x);
                ffma2(acc[j][1], hv.y, wa1.y);
                ffma2(acc[j][2], hv.y, wb1.x);
                ffma2(acc[j][3], hv.y, wb1.y);
            }
        }

        // ================= fused LSTM cell (registers) + h store =================
        {
            float* hw = hbuf + (t&1)*HBUFSZ;
            #pragma unroll
            for (int j = 0; j < 4; j++){
                float gi = fold2(acc[j][0]) + pre[j][0];
                float gf = fold2(acc[j][1]) + pre[j][1];
                float gg = fold2(acc[j][2]) + pre[j][2];
                float go = fold2(acc[j][3]) + pre[j][3];
                float i = sigf(gi);
                float f = sigf(gf);
                float g = tanh_f(gg);
                float o = sigf(go);
                float c = fmaf(f, creg[j], i*g);
                creg[j] = c;
                hw[(rbase+j)*KST + gt] = o * tanh_f(c);
            }
            if (xown) hw[xrow*KST + 64 + xj] = xreg;   // x(t+1)
        }
    }

    // final head for t = Sq-1 (pair-local sync, then read hbuf[(Sq-1)&1])
    pbar(barid);
    if (hown){
        const float* hr = hbuf + ((Sq-1)&1)*HBUFSZ + hr_*KST;
        float a0=0.f,a1=0.f,a2=0.f,a3=0.f;
        #pragma unroll 8
        for (int k = 0; k < 64; k += 4){
            a0 = fmaf(hr[k],   wout_s[2*k     + hws], a0);
            a1 = fmaf(hr[k+1], wout_s[2*(k+1) + hws], a1);
            a2 = fmaf(hr[k+2], wout_s[2*(k+2) + hws], a2);
            a3 = fmaf(hr[k+3], wout_s[2*(k+3) + hws], a3);
        }
        float a = (a0+a1)+(a2+a3) + b_out[hws];
        float sp = (a > 15.0f) ? a : log1pf(__expf(a));
        sp += 1e-4f;
        int b = row0 + hr_;
        if (hws == 0) out[b*Sq + (Sq-1)] = sp * sc_s[hr_];
        else          out[Bq*Sq + b*Sq + (Sq-1)] = sp;
    }
}

extern "C" void kernel_launch(void* const* d_in, const int* in_sizes, int n_in,
                              void* d_out, int out_size)
{
    (void)in_sizes; (void)n_in; (void)out_size;
    cudaFuncSetAttribute(deepar_kernel,
                         cudaFuncAttributeMaxDynamicSharedMemorySize, SMEM_BYTES);
    deepar_kernel<<<NB, NT, SMEM_BYTES>>>(
        (const float*)d_in[0],   // target
        (const float*)d_in[1],   // covariates
        (const int*)  d_in[2],   // static_cats
        (const float*)d_in[3],   // scale
        (const float*)d_in[4],   // emb0
        (const float*)d_in[5],   // emb1
        (const float*)d_in[6],   // emb2
        (const float*)d_in[7],   // emb3
        (const float*)d_in[8],   // w_ih
        (const float*)d_in[9],   // w_hh
        (const float*)d_in[10],  // bias
        (const float*)d_in[11],  // w_out
        (const float*)d_in[12],  // b_out
        (float*)d_out);
}